// round 1
// baseline (speedup 1.0000x reference)
#include <cuda_runtime.h>

#define EPS 1e-6f

// Scratch (allocation-free rule: __device__ globals)
__device__ float g_q[16777216];   // (B*N, C) relu(x@Wq)+eps
__device__ float g_k[16777216];   // (B*N, C) relu(k)+eps
__device__ float g_v[16777216];   // (B*N, C) v
__device__ float g_y[16777216];   // (B*N, C) att + conv
__device__ float g_kmean[4096];   // (B, C)
__device__ float g_kv[262144];    // (B, h, d, e)

// ---------------------------------------------------------------------------
// fp32 SGEMM: C = A(MxK) @ B(KxN), 128x128 block tile, BK=16, 8x8 per thread,
// double-buffered smem. epi: 1 = relu+eps -> C0 ; 2 = split cols [0,1024)->
// relu+eps C0, [1024,2048)->C1 raw ; 3 = +bias -> C0. Output ld fixed = 1024.
// M,N multiples of 128; K multiple of 16 (holds for all uses).
// ---------------------------------------------------------------------------
__global__ __launch_bounds__(256, 2)
void sgemm_kernel(const float* __restrict__ A, const float* __restrict__ B,
                  float* __restrict__ C0, float* __restrict__ C1,
                  const float* __restrict__ bias,
                  int M, int N, int K, int epi)
{
    __shared__ float As[2][16][128];
    __shared__ float Bs[2][16][128];

    const int tid = threadIdx.x;
    const int bm = blockIdx.y, bn = blockIdx.x;

    const float* Ap = A + (size_t)bm * 128 * K;
    const float* Bp = B + (size_t)bn * 128;

    const int ar0 = tid >> 2;          // 0..63 (A tile row; second at +64)
    const int ac4 = (tid & 3) << 2;    // 0,4,8,12 (A tile k-col)
    const int br0 = tid >> 5;          // 0..7  (B tile k-row; second at +8)
    const int bc4 = (tid & 31) << 2;   // 0..124 (B tile col)

    float4 ra0, ra1, rb0, rb1;

    auto loadG = [&](int kt) {
        const float* pa = Ap + (size_t)ar0 * K + kt * 16 + ac4;
        ra0 = *(const float4*)pa;
        ra1 = *(const float4*)(pa + (size_t)64 * K);
        const float* pb = Bp + (size_t)(kt * 16 + br0) * N + bc4;
        rb0 = *(const float4*)pb;
        rb1 = *(const float4*)(pb + (size_t)8 * N);
    };
    auto storeS = [&](int buf) {
        As[buf][ac4 + 0][ar0] = ra0.x; As[buf][ac4 + 1][ar0] = ra0.y;
        As[buf][ac4 + 2][ar0] = ra0.z; As[buf][ac4 + 3][ar0] = ra0.w;
        As[buf][ac4 + 0][ar0 + 64] = ra1.x; As[buf][ac4 + 1][ar0 + 64] = ra1.y;
        As[buf][ac4 + 2][ar0 + 64] = ra1.z; As[buf][ac4 + 3][ar0 + 64] = ra1.w;
        *(float4*)&Bs[buf][br0][bc4]     = rb0;
        *(float4*)&Bs[buf][br0 + 8][bc4] = rb1;
    };

    loadG(0);
    storeS(0);
    __syncthreads();

    const int tr8 = (tid >> 4) << 3;
    const int tc8 = (tid & 15) << 3;

    float acc[8][8];
    #pragma unroll
    for (int i = 0; i < 8; ++i)
        #pragma unroll
        for (int j = 0; j < 8; ++j) acc[i][j] = 0.f;

    const int nk = K >> 4;
    int buf = 0;
    for (int kt = 0; kt < nk; ++kt) {
        if (kt + 1 < nk) loadG(kt + 1);
        #pragma unroll
        for (int kk = 0; kk < 16; ++kk) {
            float a[8], b[8];
            *(float4*)&a[0] = *(const float4*)&As[buf][kk][tr8];
            *(float4*)&a[4] = *(const float4*)&As[buf][kk][tr8 + 4];
            *(float4*)&b[0] = *(const float4*)&Bs[buf][kk][tc8];
            *(float4*)&b[4] = *(const float4*)&Bs[buf][kk][tc8 + 4];
            #pragma unroll
            for (int i = 0; i < 8; ++i)
                #pragma unroll
                for (int j = 0; j < 8; ++j)
                    acc[i][j] = fmaf(a[i], b[j], acc[i][j]);
        }
        if (kt + 1 < nk) storeS(buf ^ 1);
        __syncthreads();
        buf ^= 1;
    }

    const int rbase = bm * 128 + tr8;
    const int cbase = bn * 128 + tc8;

    if (epi == 1) {
        #pragma unroll
        for (int i = 0; i < 8; ++i) {
            float* cp = C0 + (size_t)(rbase + i) * 1024 + cbase;
            #pragma unroll
            for (int j4 = 0; j4 < 2; ++j4) {
                float4 o;
                o.x = fmaxf(acc[i][j4 * 4 + 0], 0.f) + EPS;
                o.y = fmaxf(acc[i][j4 * 4 + 1], 0.f) + EPS;
                o.z = fmaxf(acc[i][j4 * 4 + 2], 0.f) + EPS;
                o.w = fmaxf(acc[i][j4 * 4 + 3], 0.f) + EPS;
                *(float4*)(cp + j4 * 4) = o;
            }
        }
    } else if (epi == 2) {
        const bool isK = (cbase < 1024);
        float* C = isK ? C0 : C1;
        const int cc = isK ? cbase : (cbase - 1024);
        #pragma unroll
        for (int i = 0; i < 8; ++i) {
            float* cp = C + (size_t)(rbase + i) * 1024 + cc;
            #pragma unroll
            for (int j4 = 0; j4 < 2; ++j4) {
                float4 o;
                if (isK) {
                    o.x = fmaxf(acc[i][j4 * 4 + 0], 0.f) + EPS;
                    o.y = fmaxf(acc[i][j4 * 4 + 1], 0.f) + EPS;
                    o.z = fmaxf(acc[i][j4 * 4 + 2], 0.f) + EPS;
                    o.w = fmaxf(acc[i][j4 * 4 + 3], 0.f) + EPS;
                } else {
                    o.x = acc[i][j4 * 4 + 0];
                    o.y = acc[i][j4 * 4 + 1];
                    o.z = acc[i][j4 * 4 + 2];
                    o.w = acc[i][j4 * 4 + 3];
                }
                *(float4*)(cp + j4 * 4) = o;
            }
        }
    } else { // epi == 3: + bias
        #pragma unroll
        for (int i = 0; i < 8; ++i) {
            float* cp = C0 + (size_t)(rbase + i) * 1024 + cbase;
            #pragma unroll
            for (int j4 = 0; j4 < 2; ++j4) {
                float4 bb = *(const float4*)(bias + cbase + j4 * 4);
                float4 o;
                o.x = acc[i][j4 * 4 + 0] + bb.x;
                o.y = acc[i][j4 * 4 + 1] + bb.y;
                o.z = acc[i][j4 * 4 + 2] + bb.z;
                o.w = acc[i][j4 * 4 + 3] + bb.w;
                *(float4*)(cp + j4 * 4) = o;
            }
        }
    }
}

// ---------------------------------------------------------------------------
// k_mean[b,c] = (1/4096) sum_n k[b,n,c].  grid (4, B, 16 n-splits), block 256.
// g_kmean pre-zeroed by memset.
// ---------------------------------------------------------------------------
__global__ void kmean_kernel(const float* __restrict__ k, float* __restrict__ km)
{
    const int c = blockIdx.x * 256 + threadIdx.x;
    const int b = blockIdx.y;
    const int n0 = blockIdx.z * 256;
    const float* p = k + ((size_t)(b * 4096 + n0)) * 1024 + c;
    float s = 0.f;
    #pragma unroll 8
    for (int n = 0; n < 256; ++n) s += p[(size_t)n * 1024];
    atomicAdd(&km[b * 1024 + c], s * (1.0f / 4096.0f));
}

// ---------------------------------------------------------------------------
// kv[b,h,d,e] = (1/4096) sum_n k[b,n,h,d] * v[b,n,h,e]
// grid (4 n-chunks, 16 h, 4 b), block 256 (16x16 threads, 4x4 outputs each).
// g_kv pre-zeroed; partial sums via atomicAdd.
// ---------------------------------------------------------------------------
__global__ __launch_bounds__(256)
void kvmat_kernel(const float* __restrict__ k, const float* __restrict__ v,
                  float* __restrict__ kv)
{
    __shared__ float Ks[32][64];
    __shared__ float Vs[32][64];
    const int tid = threadIdx.x;
    const int nc = blockIdx.x, h = blockIdx.y, b = blockIdx.z;
    const int lr = tid >> 4;
    const int lc = (tid & 15) << 2;
    const int tr = (tid >> 4) << 2;
    const int tc = (tid & 15) << 2;

    float acc[4][4];
    #pragma unroll
    for (int i = 0; i < 4; ++i)
        #pragma unroll
        for (int j = 0; j < 4; ++j) acc[i][j] = 0.f;

    const size_t base = ((size_t)(b * 4096 + nc * 1024)) * 1024 + h * 64;
    for (int t = 0; t < 1024; t += 32) {
        const float* kp = k + base + (size_t)(t + lr) * 1024 + lc;
        const float* vp = v + base + (size_t)(t + lr) * 1024 + lc;
        *(float4*)&Ks[lr][lc]      = *(const float4*)kp;
        *(float4*)&Ks[lr + 16][lc] = *(const float4*)(kp + (size_t)16 * 1024);
        *(float4*)&Vs[lr][lc]      = *(const float4*)vp;
        *(float4*)&Vs[lr + 16][lc] = *(const float4*)(vp + (size_t)16 * 1024);
        __syncthreads();
        #pragma unroll
        for (int nn = 0; nn < 32; ++nn) {
            float a[4], bb[4];
            *(float4*)a  = *(const float4*)&Ks[nn][tr];
            *(float4*)bb = *(const float4*)&Vs[nn][tc];
            #pragma unroll
            for (int i = 0; i < 4; ++i)
                #pragma unroll
                for (int j = 0; j < 4; ++j)
                    acc[i][j] = fmaf(a[i], bb[j], acc[i][j]);
        }
        __syncthreads();
    }
    #pragma unroll
    for (int i = 0; i < 4; ++i)
        #pragma unroll
        for (int j = 0; j < 4; ++j)
            atomicAdd(&kv[(size_t)((b * 16 + h) * 64 + tr + i) * 64 + tc + j],
                      acc[i][j] * (1.0f / 4096.0f));
}

// ---------------------------------------------------------------------------
// att[b,n,h,e] = z * sum_d q[b,n,h,d] * kv[b,h,d,e],
// z = 1/(sum_d q*k_mean + eps).  Writes '=' into y.
// grid (32 n-chunks of 128, 16 h, 4 b), block 128 (1 row per thread).
// ---------------------------------------------------------------------------
__global__ __launch_bounds__(128)
void att_kernel(const float* __restrict__ q, const float* __restrict__ kvm,
                const float* __restrict__ km, float* __restrict__ y)
{
    __shared__ float kvs[64][64];
    __shared__ float kms[64];
    const int b = blockIdx.z, h = blockIdx.y;
    const int n = blockIdx.x * 128 + threadIdx.x;

    const float* kvp = kvm + (size_t)(b * 16 + h) * 4096;
    for (int i = threadIdx.x; i < 1024; i += 128)
        ((float4*)kvs)[i] = ((const float4*)kvp)[i];
    if (threadIdx.x < 16)
        ((float4*)kms)[threadIdx.x] =
            ((const float4*)(km + b * 1024 + h * 64))[threadIdx.x];
    __syncthreads();

    const size_t off = ((size_t)(b * 4096 + n)) * 1024 + h * 64;
    float qr[64];
    #pragma unroll
    for (int i = 0; i < 16; ++i)
        *(float4*)&qr[i * 4] = *(const float4*)(q + off + i * 4);

    float zd = EPS;
    #pragma unroll
    for (int d = 0; d < 64; ++d) zd = fmaf(qr[d], kms[d], zd);
    const float z = 1.0f / zd;

    float* yp = y + off;
    #pragma unroll
    for (int e0 = 0; e0 < 64; e0 += 8) {
        float s0 = 0.f, s1 = 0.f, s2 = 0.f, s3 = 0.f;
        float s4 = 0.f, s5 = 0.f, s6 = 0.f, s7 = 0.f;
        #pragma unroll
        for (int d = 0; d < 64; ++d) {
            const float4 k0 = *(const float4*)&kvs[d][e0];
            const float4 k1 = *(const float4*)&kvs[d][e0 + 4];
            const float qd = qr[d];
            s0 = fmaf(qd, k0.x, s0); s1 = fmaf(qd, k0.y, s1);
            s2 = fmaf(qd, k0.z, s2); s3 = fmaf(qd, k0.w, s3);
            s4 = fmaf(qd, k1.x, s4); s5 = fmaf(qd, k1.y, s5);
            s6 = fmaf(qd, k1.z, s6); s7 = fmaf(qd, k1.w, s7);
        }
        float4 o0 = {s0 * z, s1 * z, s2 * z, s3 * z};
        float4 o1 = {s4 * z, s5 * z, s6 * z, s7 * z};
        *(float4*)(yp + e0) = o0;
        *(float4*)(yp + e0 + 4) = o1;
    }
}

// ---------------------------------------------------------------------------
// Depthwise 5x5 SAME conv on v viewed as (B*h, d=64 chans, 64, 64), += into y.
// grid (16 x-tiles of 4, 8 y-strips of 8, 64 b*h), block 256 = (e:64, x:4).
// Sliding 5x5 register window: 12 row-loads for 8 outputs per thread.
// ---------------------------------------------------------------------------
__global__ __launch_bounds__(256)
void conv_kernel(const float* __restrict__ v, const float* __restrict__ w,
                 const float* __restrict__ wb, float* __restrict__ y)
{
    const int e  = threadIdx.x & 63;
    const int xg = threadIdx.x >> 6;
    const int x  = blockIdx.x * 4 + xg;
    const int y0 = blockIdx.y * 8;
    const int bh = blockIdx.z;
    const int b = bh >> 4, h = bh & 15;

    float wgt[25];
    #pragma unroll
    for (int i = 0; i < 25; ++i) wgt[i] = w[e * 25 + i];
    const float bias = wb[e];

    const float* vb = v + (size_t)b * 4096 * 1024 + h * 64 + e;
    float* yb = y + (size_t)b * 4096 * 1024 + h * 64 + e;

    float win[5][5];
    #pragma unroll
    for (int r = 0; r < 4; ++r) {
        const int yy = y0 - 2 + r;
        #pragma unroll
        for (int c = 0; c < 5; ++c) {
            const int xx = x - 2 + c;
            win[r][c] = (yy >= 0 && yy < 64 && xx >= 0 && xx < 64)
                        ? vb[(size_t)(yy * 64 + xx) * 1024] : 0.f;
        }
    }

    #pragma unroll
    for (int oy = 0; oy < 8; ++oy) {
        const int yy = y0 + oy + 2;
        #pragma unroll
        for (int c = 0; c < 5; ++c) {
            const int xx = x - 2 + c;
            win[4][c] = (yy < 64 && xx >= 0 && xx < 64)
                        ? vb[(size_t)(yy * 64 + xx) * 1024] : 0.f;
        }
        float acc = bias;
        #pragma unroll
        for (int r = 0; r < 5; ++r)
            #pragma unroll
            for (int c = 0; c < 5; ++c)
                acc = fmaf(win[r][c], wgt[r * 5 + c], acc);

        yb[(size_t)((y0 + oy) * 64 + x) * 1024] += acc;

        #pragma unroll
        for (int r = 0; r < 4; ++r)
            #pragma unroll
            for (int c = 0; c < 5; ++c) win[r][c] = win[r + 1][c];
    }
}

// ---------------------------------------------------------------------------
extern "C" void kernel_launch(void* const* d_in, const int* in_sizes, int n_in,
                              void* d_out, int out_size)
{
    const float* x     = (const float*)d_in[0];
    const float* Wq    = (const float*)d_in[1];
    const float* Wkv   = (const float*)d_in[2];
    const float* Wproj = (const float*)d_in[3];
    const float* bproj = (const float*)d_in[4];
    const float* dwc_w = (const float*)d_in[5];
    const float* dwc_b = (const float*)d_in[6];
    float* out = (float*)d_out;

    float *q, *k, *v, *y, *km, *kv;
    cudaGetSymbolAddress((void**)&q,  g_q);
    cudaGetSymbolAddress((void**)&k,  g_k);
    cudaGetSymbolAddress((void**)&v,  g_v);
    cudaGetSymbolAddress((void**)&y,  g_y);
    cudaGetSymbolAddress((void**)&km, g_kmean);
    cudaGetSymbolAddress((void**)&kv, g_kv);

    cudaMemsetAsync(km, 0, 4096 * sizeof(float));
    cudaMemsetAsync(kv, 0, 262144 * sizeof(float));

    // q = relu(x @ Wq) + eps
    sgemm_kernel<<<dim3(8, 128), 256>>>(x, Wq, q, nullptr, nullptr,
                                        16384, 1024, 1024, 1);
    // kv_lin = x @ Wkv  -> k (relu+eps), v (raw)
    sgemm_kernel<<<dim3(16, 128), 256>>>(x, Wkv, k, v, nullptr,
                                         16384, 2048, 1024, 2);
    // k_mean
    kmean_kernel<<<dim3(4, 4, 16), 256>>>(k, km);
    // kv matrices
    kvmat_kernel<<<dim3(4, 16, 4), 256>>>(k, v, kv);
    // att -> y
    att_kernel<<<dim3(32, 16, 4), 128>>>(q, kv, km, y);
    // depthwise conv, += into y
    conv_kernel<<<dim3(16, 8, 64), 256>>>(v, dwc_w, dwc_b, y);
    // out = y @ Wproj + bproj
    sgemm_kernel<<<dim3(8, 128), 256>>>(y, Wproj, out, nullptr, bproj,
                                        16384, 1024, 1024, 3);
}

// round 3
// speedup vs baseline: 2.3700x; 2.3700x over previous
#include <cuda_runtime.h>
#include <cuda_bf16.h>
#include <cstdint>

#define EPS 1e-6f

// ---------------- scratch (__device__ globals; no allocations allowed) -----
__device__ float g_q[16777216];            // (16384, 1024) fp32
__device__ float g_k[16777216];
__device__ float g_v[16777216];
__device__ float g_y[16777216];
__device__ float g_kmean[4096];
__device__ float g_kv[262144];
__device__ __nv_bfloat16 g_ahi[16777216];  // A-side hi/lo bf16 (x, later y)
__device__ __nv_bfloat16 g_alo[16777216];
__device__ __nv_bfloat16 g_whi[4194304];   // transposed weights hi/lo bf16
__device__ __nv_bfloat16 g_wlo[4194304];   // [Wq_t | Wkv_t | Wproj_t]

// ---------------- PTX helpers (all baseline sm_80+ features) ---------------
__device__ __forceinline__ uint32_t smem_u32(const void* p) {
    uint32_t a;
    asm("{ .reg .u64 t; cvta.to.shared.u64 t, %1; cvt.u32.u64 %0, t; }"
        : "=r"(a) : "l"(p));
    return a;
}
__device__ __forceinline__ void cpa16(uint32_t s, const void* g) {
    asm volatile("cp.async.cg.shared.global [%0], [%1], 16;" :: "r"(s), "l"(g));
}
__device__ __forceinline__ void ldmx4(uint32_t* r, uint32_t a) {
    asm volatile("ldmatrix.sync.aligned.m8n8.x4.shared.b16 {%0,%1,%2,%3}, [%4];"
                 : "=r"(r[0]), "=r"(r[1]), "=r"(r[2]), "=r"(r[3]) : "r"(a));
}
__device__ __forceinline__ void mma16816(float* c, const uint32_t* a,
                                         uint32_t b0, uint32_t b1) {
    asm volatile(
        "mma.sync.aligned.m16n8k16.row.col.f32.bf16.bf16.f32 "
        "{%0,%1,%2,%3},{%4,%5,%6,%7},{%8,%9},{%0,%1,%2,%3};"
        : "+f"(c[0]), "+f"(c[1]), "+f"(c[2]), "+f"(c[3])
        : "r"(a[0]), "r"(a[1]), "r"(a[2]), "r"(a[3]), "r"(b0), "r"(b1));
}
// SW64 swizzle for 64-byte rows: conflict-free ldmatrix + cp.async
#define SWZ64(o) ((o) ^ (((o) >> 3) & 0x30))

// ---------------------------------------------------------------------------
// bf16 split GEMM via mma.sync: D(fp32) = Ahi*Bhi + Ahi*Blo + Alo*Bhi
// A: [M,1024] bf16 row-major (hi/lo). B: [N,1024] bf16 row-major (hi/lo,
// i.e. transposed weights). CTA tile 128x128, BK=32, 8 warps (2m x 4n).
// epi: 1 relu+eps->O0 ; 2 split col<1024 relu->O0 else raw->O1 ; 3 +bias->O0.
// Output leading dim fixed = 1024.
// ---------------------------------------------------------------------------
#define BK 32
#define T_BYTES 8192              // one 128x32 bf16 tile
#define STG (4 * T_BYTES)         // Ahi|Alo|Bhi|Blo per stage = 32KB

__global__ __launch_bounds__(256, 2)
void mma_gemm(const __nv_bfloat16* __restrict__ Ahi,
              const __nv_bfloat16* __restrict__ Alo,
              const __nv_bfloat16* __restrict__ Bhi,
              const __nv_bfloat16* __restrict__ Blo,
              float* __restrict__ O0, float* __restrict__ O1,
              const float* __restrict__ bias, int epi)
{
    extern __shared__ __align__(1024) char smraw[];
    const uint32_t sb = smem_u32(smraw);

    const int tid = threadIdx.x;
    const int wid = tid >> 5, lid = tid & 31;
    const int bm = blockIdx.y, bn = blockIdx.x;

    const int wm = (wid & 1) * 64;   // warp m-offset (2 warps)
    const int wn = (wid >> 1) * 32;  // warp n-offset (4 warps)
    const int lr = lid & 15, lc = lid >> 4;

    float acc[4][4][4];
    #pragma unroll
    for (int i = 0; i < 4; ++i)
        #pragma unroll
        for (int j = 0; j < 4; ++j)
            #pragma unroll
            for (int r = 0; r < 4; ++r) acc[i][j][r] = 0.f;

    // per-thread load slots: 2 x 16B chunks per tile (512 chunks per tile)
    const int id0 = tid, id1 = tid + 256;
    const int r0 = id0 >> 2, c0 = id0 & 3;
    const int r1 = id1 >> 2, c1 = id1 & 3;

    auto load_stage = [&](int kc, int st) {
        const uint32_t base = sb + st * STG;
        const int kofs = kc * BK;
        #pragma unroll
        for (int t = 0; t < 4; ++t) {
            const __nv_bfloat16* src = (t == 0) ? Ahi : (t == 1) ? Alo
                                     : (t == 2) ? Bhi : Blo;
            const int rowbase = (t < 2) ? bm * 128 : bn * 128;
            const uint32_t tb = base + t * T_BYTES;
            cpa16(tb + SWZ64(r0 * 64 + c0 * 16),
                  src + (size_t)(rowbase + r0) * 1024 + kofs + c0 * 8);
            cpa16(tb + SWZ64(r1 * 64 + c1 * 16),
                  src + (size_t)(rowbase + r1) * 1024 + kofs + c1 * 8);
        }
        asm volatile("cp.async.commit_group;" ::: "memory");
    };

    auto compute = [&](int st) {
        const uint32_t base = sb + st * STG;
        #pragma unroll
        for (int ks = 0; ks < 2; ++ks) {
            uint32_t ah[4][4], al[4][4];
            #pragma unroll
            for (int mi = 0; mi < 4; ++mi) {
                uint32_t off = SWZ64((wm + mi * 16 + lr) * 64 + (ks * 2 + lc) * 16);
                ldmx4(ah[mi], base + off);
                ldmx4(al[mi], base + T_BYTES + off);
            }
            uint32_t bh[2][4], bl[2][4];
            #pragma unroll
            for (int nj = 0; nj < 2; ++nj) {
                uint32_t off = SWZ64((wn + nj * 16 + lr) * 64 + (ks * 2 + lc) * 16);
                ldmx4(bh[nj], base + 2 * T_BYTES + off);
                ldmx4(bl[nj], base + 3 * T_BYTES + off);
            }
            #pragma unroll
            for (int mi = 0; mi < 4; ++mi)
                #pragma unroll
                for (int ni = 0; ni < 4; ++ni) {
                    const int nj = ni >> 1, s = ni & 1;
                    mma16816(acc[mi][ni], ah[mi], bh[nj][s], bh[nj][s + 2]);
                    mma16816(acc[mi][ni], ah[mi], bl[nj][s], bl[nj][s + 2]);
                    mma16816(acc[mi][ni], al[mi], bh[nj][s], bh[nj][s + 2]);
                }
        }
    };

    load_stage(0, 0);
    const int NK = 1024 / BK;   // 32
    for (int kc = 0; kc < NK; ++kc) {
        const int st = kc & 1;
        if (kc + 1 < NK) {
            load_stage(kc + 1, st ^ 1);
            asm volatile("cp.async.wait_group 1;" ::: "memory");
        } else {
            asm volatile("cp.async.wait_group 0;" ::: "memory");
        }
        __syncthreads();
        compute(st);
        __syncthreads();
    }

    // ---------------- epilogue ----------------
    const int qrow = lid >> 2;
    const int qcol = (lid & 3) * 2;
    #pragma unroll
    for (int mi = 0; mi < 4; ++mi) {
        #pragma unroll
        for (int ni = 0; ni < 4; ++ni) {
            const int gn = bn * 128 + wn + ni * 8 + qcol;
            #pragma unroll
            for (int half = 0; half < 2; ++half) {
                const int gm = bm * 128 + wm + mi * 16 + qrow + half * 8;
                float v0 = acc[mi][ni][half * 2 + 0];
                float v1 = acc[mi][ni][half * 2 + 1];
                if (epi == 1) {
                    v0 = fmaxf(v0, 0.f) + EPS;
                    v1 = fmaxf(v1, 0.f) + EPS;
                    *(float2*)(O0 + (size_t)gm * 1024 + gn) = make_float2(v0, v1);
                } else if (epi == 2) {
                    if (gn < 1024) {
                        v0 = fmaxf(v0, 0.f) + EPS;
                        v1 = fmaxf(v1, 0.f) + EPS;
                        *(float2*)(O0 + (size_t)gm * 1024 + gn) = make_float2(v0, v1);
                    } else {
                        *(float2*)(O1 + (size_t)gm * 1024 + gn - 1024) =
                            make_float2(v0, v1);
                    }
                } else {
                    const float2 bb = *(const float2*)(bias + gn);
                    *(float2*)(O0 + (size_t)gm * 1024 + gn) =
                        make_float2(v0 + bb.x, v1 + bb.y);
                }
            }
        }
    }
}

// ---------------------------------------------------------------------------
// hi/lo bf16 split of an fp32 array (vectorized by 4)
// ---------------------------------------------------------------------------
__global__ void asplit(const float4* __restrict__ X,
                       __nv_bfloat162* __restrict__ Hi,
                       __nv_bfloat162* __restrict__ Lo, int n4)
{
    int i = blockIdx.x * 256 + threadIdx.x;
    if (i >= n4) return;
    float4 v = X[i];
    __nv_bfloat16 h0 = __float2bfloat16(v.x), h1 = __float2bfloat16(v.y);
    __nv_bfloat16 h2 = __float2bfloat16(v.z), h3 = __float2bfloat16(v.w);
    __nv_bfloat16 l0 = __float2bfloat16(v.x - __bfloat162float(h0));
    __nv_bfloat16 l1 = __float2bfloat16(v.y - __bfloat162float(h1));
    __nv_bfloat16 l2 = __float2bfloat16(v.z - __bfloat162float(h2));
    __nv_bfloat16 l3 = __float2bfloat16(v.w - __bfloat162float(h3));
    Hi[2 * i]     = __halves2bfloat162(h0, h1);
    Hi[2 * i + 1] = __halves2bfloat162(h2, h3);
    Lo[2 * i]     = __halves2bfloat162(l0, l1);
    Lo[2 * i + 1] = __halves2bfloat162(l2, l3);
}

// ---------------------------------------------------------------------------
// transpose + hi/lo split of weight W[K,N] -> T[N,K] bf16
// ---------------------------------------------------------------------------
__global__ void wtsplit(const float* __restrict__ W,
                        __nv_bfloat16* __restrict__ Thi,
                        __nv_bfloat16* __restrict__ Tlo, int K, int N)
{
    __shared__ float t[32][33];
    const int n0 = blockIdx.x * 32, k0 = blockIdx.y * 32;
    const int tx = threadIdx.x, ty = threadIdx.y;
    #pragma unroll
    for (int i = 0; i < 32; i += 8)
        t[ty + i][tx] = W[(size_t)(k0 + ty + i) * N + n0 + tx];
    __syncthreads();
    #pragma unroll
    for (int i = 0; i < 32; i += 8) {
        float v = t[tx][ty + i];
        __nv_bfloat16 h = __float2bfloat16(v);
        __nv_bfloat16 l = __float2bfloat16(v - __bfloat162float(h));
        Thi[(size_t)(n0 + ty + i) * K + k0 + tx] = h;
        Tlo[(size_t)(n0 + ty + i) * K + k0 + tx] = l;
    }
}

// ---------------------------------------------------------------------------
// k_mean[b,c] = (1/4096) sum_n k[b,n,c]
// ---------------------------------------------------------------------------
__global__ void kmean_kernel(const float* __restrict__ k, float* __restrict__ km)
{
    const int c = blockIdx.x * 256 + threadIdx.x;
    const int b = blockIdx.y;
    const int n0 = blockIdx.z * 256;
    const float* p = k + ((size_t)(b * 4096 + n0)) * 1024 + c;
    float s = 0.f;
    #pragma unroll 8
    for (int n = 0; n < 256; ++n) s += p[(size_t)n * 1024];
    atomicAdd(&km[b * 1024 + c], s * (1.0f / 4096.0f));
}

// ---------------------------------------------------------------------------
// kv[b,h,d,e] = (1/4096) sum_n k[b,n,h,d] * v[b,n,h,e]   (16 n-chunks)
// ---------------------------------------------------------------------------
__global__ __launch_bounds__(256)
void kvmat_kernel(const float* __restrict__ k, const float* __restrict__ v,
                  float* __restrict__ kv)
{
    __shared__ float Ks[32][64];
    __shared__ float Vs[32][64];
    const int tid = threadIdx.x;
    const int nc = blockIdx.x, h = blockIdx.y, b = blockIdx.z;
    const int lr = tid >> 4;
    const int lc = (tid & 15) << 2;
    const int tr = (tid >> 4) << 2;
    const int tc = (tid & 15) << 2;

    float acc[4][4];
    #pragma unroll
    for (int i = 0; i < 4; ++i)
        #pragma unroll
        for (int j = 0; j < 4; ++j) acc[i][j] = 0.f;

    const size_t base = ((size_t)(b * 4096 + nc * 256)) * 1024 + h * 64;
    for (int t = 0; t < 256; t += 32) {
        const float* kp = k + base + (size_t)(t + lr) * 1024 + lc;
        const float* vp = v + base + (size_t)(t + lr) * 1024 + lc;
        *(float4*)&Ks[lr][lc]      = *(const float4*)kp;
        *(float4*)&Ks[lr + 16][lc] = *(const float4*)(kp + (size_t)16 * 1024);
        *(float4*)&Vs[lr][lc]      = *(const float4*)vp;
        *(float4*)&Vs[lr + 16][lc] = *(const float4*)(vp + (size_t)16 * 1024);
        __syncthreads();
        #pragma unroll
        for (int nn = 0; nn < 32; ++nn) {
            float a[4], bb[4];
            *(float4*)a  = *(const float4*)&Ks[nn][tr];
            *(float4*)bb = *(const float4*)&Vs[nn][tc];
            #pragma unroll
            for (int i = 0; i < 4; ++i)
                #pragma unroll
                for (int j = 0; j < 4; ++j)
                    acc[i][j] = fmaf(a[i], bb[j], acc[i][j]);
        }
        __syncthreads();
    }
    #pragma unroll
    for (int i = 0; i < 4; ++i)
        #pragma unroll
        for (int j = 0; j < 4; ++j)
            atomicAdd(&kv[(size_t)((b * 16 + h) * 64 + tr + i) * 64 + tc + j],
                      acc[i][j] * (1.0f / 4096.0f));
}

// ---------------------------------------------------------------------------
// att -> y (writes '=')
// ---------------------------------------------------------------------------
__global__ __launch_bounds__(128)
void att_kernel(const float* __restrict__ q, const float* __restrict__ kvm,
                const float* __restrict__ km, float* __restrict__ y)
{
    __shared__ float kvs[64][64];
    __shared__ float kms[64];
    const int b = blockIdx.z, h = blockIdx.y;
    const int n = blockIdx.x * 128 + threadIdx.x;

    const float* kvp = kvm + (size_t)(b * 16 + h) * 4096;
    for (int i = threadIdx.x; i < 1024; i += 128)
        ((float4*)kvs)[i] = ((const float4*)kvp)[i];
    if (threadIdx.x < 16)
        ((float4*)kms)[threadIdx.x] =
            ((const float4*)(km + b * 1024 + h * 64))[threadIdx.x];
    __syncthreads();

    const size_t off = ((size_t)(b * 4096 + n)) * 1024 + h * 64;
    float qr[64];
    #pragma unroll
    for (int i = 0; i < 16; ++i)
        *(float4*)&qr[i * 4] = *(const float4*)(q + off + i * 4);

    float zd = EPS;
    #pragma unroll
    for (int d = 0; d < 64; ++d) zd = fmaf(qr[d], kms[d], zd);
    const float z = 1.0f / zd;

    float* yp = y + off;
    #pragma unroll
    for (int e0 = 0; e0 < 64; e0 += 8) {
        float s0 = 0.f, s1 = 0.f, s2 = 0.f, s3 = 0.f;
        float s4 = 0.f, s5 = 0.f, s6 = 0.f, s7 = 0.f;
        #pragma unroll
        for (int d = 0; d < 64; ++d) {
            const float4 k0 = *(const float4*)&kvs[d][e0];
            const float4 k1 = *(const float4*)&kvs[d][e0 + 4];
            const float qd = qr[d];
            s0 = fmaf(qd, k0.x, s0); s1 = fmaf(qd, k0.y, s1);
            s2 = fmaf(qd, k0.z, s2); s3 = fmaf(qd, k0.w, s3);
            s4 = fmaf(qd, k1.x, s4); s5 = fmaf(qd, k1.y, s5);
            s6 = fmaf(qd, k1.z, s6); s7 = fmaf(qd, k1.w, s7);
        }
        float4 o0 = {s0 * z, s1 * z, s2 * z, s3 * z};
        float4 o1 = {s4 * z, s5 * z, s6 * z, s7 * z};
        *(float4*)(yp + e0) = o0;
        *(float4*)(yp + e0 + 4) = o1;
    }
}

// ---------------------------------------------------------------------------
// depthwise 5x5 SAME conv, += into y
// ---------------------------------------------------------------------------
__global__ __launch_bounds__(256)
void conv_kernel(const float* __restrict__ v, const float* __restrict__ w,
                 const float* __restrict__ wb, float* __restrict__ y)
{
    const int e  = threadIdx.x & 63;
    const int xg = threadIdx.x >> 6;
    const int x  = blockIdx.x * 4 + xg;
    const int y0 = blockIdx.y * 8;
    const int bh = blockIdx.z;
    const int b = bh >> 4, h = bh & 15;

    float wgt[25];
    #pragma unroll
    for (int i = 0; i < 25; ++i) wgt[i] = w[e * 25 + i];
    const float bias = wb[e];

    const float* vb = v + (size_t)b * 4096 * 1024 + h * 64 + e;
    float* yb = y + (size_t)b * 4096 * 1024 + h * 64 + e;

    float win[5][5];
    #pragma unroll
    for (int r = 0; r < 4; ++r) {
        const int yy = y0 - 2 + r;
        #pragma unroll
        for (int c = 0; c < 5; ++c) {
            const int xx = x - 2 + c;
            win[r][c] = (yy >= 0 && yy < 64 && xx >= 0 && xx < 64)
                        ? vb[(size_t)(yy * 64 + xx) * 1024] : 0.f;
        }
    }

    #pragma unroll
    for (int oy = 0; oy < 8; ++oy) {
        const int yy = y0 + oy + 2;
        #pragma unroll
        for (int c = 0; c < 5; ++c) {
            const int xx = x - 2 + c;
            win[4][c] = (yy < 64 && xx >= 0 && xx < 64)
                        ? vb[(size_t)(yy * 64 + xx) * 1024] : 0.f;
        }
        float acc = bias;
        #pragma unroll
        for (int r = 0; r < 5; ++r)
            #pragma unroll
            for (int c = 0; c < 5; ++c)
                acc = fmaf(win[r][c], wgt[r * 5 + c], acc);

        yb[(size_t)((y0 + oy) * 64 + x) * 1024] += acc;

        #pragma unroll
        for (int r = 0; r < 4; ++r)
            #pragma unroll
            for (int c = 0; c < 5; ++c) win[r][c] = win[r + 1][c];
    }
}

// ---------------------------------------------------------------------------
extern "C" void kernel_launch(void* const* d_in, const int* in_sizes, int n_in,
                              void* d_out, int out_size)
{
    const float* x     = (const float*)d_in[0];
    const float* Wq    = (const float*)d_in[1];
    const float* Wkv   = (const float*)d_in[2];
    const float* Wproj = (const float*)d_in[3];
    const float* bproj = (const float*)d_in[4];
    const float* dwc_w = (const float*)d_in[5];
    const float* dwc_b = (const float*)d_in[6];
    float* out = (float*)d_out;

    float *q, *k, *v, *y, *km, *kv;
    __nv_bfloat16 *ahi, *alo, *whi, *wlo;
    cudaGetSymbolAddress((void**)&q,   g_q);
    cudaGetSymbolAddress((void**)&k,   g_k);
    cudaGetSymbolAddress((void**)&v,   g_v);
    cudaGetSymbolAddress((void**)&y,   g_y);
    cudaGetSymbolAddress((void**)&km,  g_kmean);
    cudaGetSymbolAddress((void**)&kv,  g_kv);
    cudaGetSymbolAddress((void**)&ahi, g_ahi);
    cudaGetSymbolAddress((void**)&alo, g_alo);
    cudaGetSymbolAddress((void**)&whi, g_whi);
    cudaGetSymbolAddress((void**)&wlo, g_wlo);

    cudaFuncSetAttribute(mma_gemm, cudaFuncAttributeMaxDynamicSharedMemorySize,
                         2 * STG);

    cudaMemsetAsync(km, 0, 4096 * sizeof(float));
    cudaMemsetAsync(kv, 0, 262144 * sizeof(float));

    // split x; transpose+split weights
    asplit<<<16384, 256>>>((const float4*)x, (__nv_bfloat162*)ahi,
                           (__nv_bfloat162*)alo, 4194304);
    wtsplit<<<dim3(32, 32), dim3(32, 8)>>>(Wq,    whi,           wlo,           1024, 1024);
    wtsplit<<<dim3(64, 32), dim3(32, 8)>>>(Wkv,   whi + 1048576, wlo + 1048576, 1024, 2048);
    wtsplit<<<dim3(32, 32), dim3(32, 8)>>>(Wproj, whi + 3145728, wlo + 3145728, 1024, 1024);

    const size_t smem = 2 * STG;
    // q = relu(x@Wq)+eps
    mma_gemm<<<dim3(8, 128), 256, smem>>>(ahi, alo, whi, wlo, q, nullptr,
                                          nullptr, 1);
    // kv_lin = x@Wkv -> k (relu+eps), v
    mma_gemm<<<dim3(16, 128), 256, smem>>>(ahi, alo, whi + 1048576,
                                           wlo + 1048576, k, v, nullptr, 2);

    kmean_kernel<<<dim3(4, 4, 16), 256>>>(k, km);
    kvmat_kernel<<<dim3(16, 16, 4), 256>>>(k, v, kv);
    att_kernel<<<dim3(32, 16, 4), 128>>>(q, kv, km, y);
    conv_kernel<<<dim3(16, 8, 64), 256>>>(v, dwc_w, dwc_b, y);

    // split y; out = y@Wproj + bproj
    asplit<<<16384, 256>>>((const float4*)y, (__nv_bfloat162*)ahi,
                           (__nv_bfloat162*)alo, 4194304);
    mma_gemm<<<dim3(8, 128), 256, smem>>>(ahi, alo, whi + 3145728,
                                          wlo + 3145728, out, nullptr, bproj, 3);
}